// round 1
// baseline (speedup 1.0000x reference)
#include <cuda_runtime.h>
#include <cuda_bf16.h>

#define BINS     10
#define THREADS  256
#define GRID     1184   // 148 SMs * 8 CTAs

// Global scratch (no allocations allowed) — per-bin bce-sum and count.
__device__ float g_binS[BINS];
__device__ float g_binC[BINS];

__global__ void ghm_init_kernel() {
    int i = threadIdx.x;
    if (i < BINS) { g_binS[i] = 0.0f; g_binC[i] = 0.0f; }
}

// Per-element processing: matches reference bit-for-bit on the bin index
// (g computed as |p - t| in fp32, idx = trunc(g*10) clipped to 9).
// bce = -(t*log(p) + (1-t)*log(1-p)) = -log(t!=0 ? p : 1-p), t in {0,1}.
__device__ __forceinline__ void ghm_accum(float p, float t, float2* hist_tid) {
    float g   = fabsf(p - t);
    int   idx = (int)(g * 10.0f);          // g >= 0, trunc == floor
    idx = min(idx, BINS - 1);
    float q   = (t != 0.0f) ? p : (1.0f - p);
    float bce = -__logf(q);
    // Per-thread-private slot: hist[idx*THREADS + tid]. All 32 lanes of a
    // warp hit distinct 8B-aligned consecutive-lane addresses -> conflict-free.
    float2* slot = hist_tid + idx * THREADS;
    float2  a = *slot;
    a.x += bce;
    a.y += 1.0f;
    *slot = a;
}

__global__ void __launch_bounds__(THREADS)
ghm_main_kernel(const float* __restrict__ inp,
                const float* __restrict__ tgt,
                int n4, int n) {
    __shared__ float2 hist[BINS * THREADS];   // 20 KB: [bin][tid]
    const int tid = threadIdx.x;

    #pragma unroll
    for (int b = 0; b < BINS; b++)
        hist[b * THREADS + tid] = make_float2(0.0f, 0.0f);
    __syncthreads();

    float2* hist_tid = &hist[tid];

    const float4* __restrict__ P4 = (const float4*)inp;
    const float4* __restrict__ T4 = (const float4*)tgt;

    // Grid-stride over float4 pairs (2x LDG.128 per iteration).
    for (int i = blockIdx.x * THREADS + tid; i < n4; i += GRID * THREADS) {
        float4 p = P4[i];
        float4 t = T4[i];
        ghm_accum(p.x, t.x, hist_tid);
        ghm_accum(p.y, t.y, hist_tid);
        ghm_accum(p.z, t.z, hist_tid);
        ghm_accum(p.w, t.w, hist_tid);
    }
    // Scalar tail (n not divisible by 4).
    for (int i = n4 * 4 + blockIdx.x * THREADS + tid; i < n; i += GRID * THREADS)
        ghm_accum(inp[i], tgt[i], hist_tid);

    __syncthreads();

    // CTA tree reduction over the thread dimension, all bins per level.
    for (int s = THREADS / 2; s > 0; s >>= 1) {
        if (tid < s) {
            #pragma unroll
            for (int b = 0; b < BINS; b++) {
                float2 a = hist[b * THREADS + tid];
                float2 c = hist[b * THREADS + tid + s];
                hist[b * THREADS + tid] = make_float2(a.x + c.x, a.y + c.y);
            }
        }
        __syncthreads();
    }

    if (tid < BINS) {
        atomicAdd(&g_binS[tid], hist[tid * THREADS].x);
        atomicAdd(&g_binC[tid], hist[tid * THREADS].y);
    }
}

__global__ void ghm_finalize_kernel(float* __restrict__ out) {
    // loss = (1/max(n,1)) * sum_b S_b / C_b over non-empty bins.
    float n = 0.0f, acc = 0.0f;
    #pragma unroll
    for (int b = 0; b < BINS; b++) {
        float c = g_binC[b];
        if (c > 0.0f) {
            n   += 1.0f;
            acc += g_binS[b] / c;
        }
    }
    out[0] = acc / fmaxf(n, 1.0f);
}

extern "C" void kernel_launch(void* const* d_in, const int* in_sizes, int n_in,
                              void* d_out, int out_size) {
    const float* inp = (const float*)d_in[0];
    const float* tgt = (const float*)d_in[1];
    float* out = (float*)d_out;
    int n  = in_sizes[0];
    int n4 = n >> 2;

    ghm_init_kernel<<<1, 32>>>();
    ghm_main_kernel<<<GRID, THREADS>>>(inp, tgt, n4, n);
    ghm_finalize_kernel<<<1, 1>>>(out);
}